// round 1
// baseline (speedup 1.0000x reference)
#include <cuda_runtime.h>

#define TT 2048
#define NB 512
#define NH 13
#define NG 52

__device__ __forceinline__ float sigm(float x) {
    return 1.0f / (1.0f + __expf(-x));
}

// NaN-safe tanh via exp on |x|; accurate to ~1e-6, no overflow for any x.
__device__ __forceinline__ float tanh_fast(float x) {
    float ax = fabsf(x);
    float e  = __expf(-2.0f * ax);
    float r  = __fdividef(1.0f - e, 1.0f + e);
    return copysignf(r, x);
}

__device__ __forceinline__ float fc_head(const float* hb, const float* fcw, float fcb) {
    const float4* hr = reinterpret_cast<const float4*>(hb);
    const float4 hA = hr[0], hB = hr[1], hC = hr[2];
    const float h12 = hb[12];
    float b0 = fmaf(hA.x, fcw[0], fcb);
    float b1 = hA.y * fcw[1];
    float b2 = hA.z * fcw[2];
    float b3 = hA.w * fcw[3];
    b0 = fmaf(hB.x, fcw[4],  b0);
    b1 = fmaf(hB.y, fcw[5],  b1);
    b2 = fmaf(hB.z, fcw[6],  b2);
    b3 = fmaf(hB.w, fcw[7],  b3);
    b0 = fmaf(hC.x, fcw[8],  b0);
    b1 = fmaf(hC.y, fcw[9],  b1);
    b2 = fmaf(hC.z, fcw[10], b2);
    b3 = fmaf(hC.w, fcw[11], b3);
    b0 = fmaf(h12,  fcw[12], b0);
    return sigm((b0 + b1) + (b2 + b3));
}

__global__ void __launch_bounds__(128)
lstm_fused(const float* __restrict__ x,
           const float* __restrict__ W_ih,
           const float* __restrict__ W_hh,
           const float* __restrict__ b_ih,
           const float* __restrict__ b_hh,
           const float* __restrict__ fc_w,
           const float* __restrict__ fc_b,
           float* __restrict__ out)
{
    // 8-deep ring of staged x rows (padded to 16 floats for LDS.128),
    // h state, and activated-gate exchange buffer. Per block: 2 sequences.
    __shared__ __align__(16) float xrow[8][2][16];
    __shared__ __align__(16) float hbuf[2][16];
    __shared__ float act[2][56];

    const int tid = threadIdx.x;
    const int s   = tid >> 6;          // local sequence 0/1
    const int g   = tid & 63;          // gate id (0..51), 52..63 = helpers
    const int seq = blockIdx.x * 2 + s;
    const float* xb = x + (size_t)seq * TT * NH;

    // Per-thread constant weights in registers.
    float wi[13], wh[13], bias = 0.0f;
    if (g < NG) {
        #pragma unroll
        for (int k2 = 0; k2 < 13; k2++) {
            wi[k2] = W_ih[g * 13 + k2];
            wh[k2] = W_hh[g * 13 + k2];
        }
        bias = b_ih[g] + b_hh[g];
    }
    float fcw[13], fcb = 0.0f;
    if (g == 63) {
        #pragma unroll
        for (int k2 = 0; k2 < 13; k2++) fcw[k2] = fc_w[k2];
        fcb = fc_b[0];
    }
    if (g < 16) hbuf[s][g] = 0.0f;     // h0 = 0 (pads too)

    // x prefetch pipeline: lanes 52..63 own element k = g-52; lane 52 also owns k=12.
    float p[4], q[4];
    const int k = g - 52;
    if (g >= 52) {
        #pragma unroll
        for (int t0 = 0; t0 < 4; t0++) {
            xrow[t0][s][k] = xb[t0 * 13 + k];
            if (k == 0) xrow[t0][s][12] = xb[t0 * 13 + 12];
        }
        #pragma unroll
        for (int u = 0; u < 4; u++) {
            p[u] = xb[(4 + u) * 13 + k];
            if (k == 0) q[u] = xb[(4 + u) * 13 + 12];
        }
    }

    float c = 0.0f;
    __syncthreads();

    for (int t = 0; t < TT; t += 4) {
        #pragma unroll
        for (int u = 0; u < 4; u++) {
            const int tt = t + u;
            float a = 0.0f;
            if (g < NG) {
                // ---- phase 1: gate pre-activation (x-dot + h-dot) ----
                const float4* xr = reinterpret_cast<const float4*>(&xrow[tt & 7][s][0]);
                const float4 xA = xr[0], xB = xr[1], xC = xr[2];
                const float x12 = xrow[tt & 7][s][12];
                const float4* hr = reinterpret_cast<const float4*>(&hbuf[s][0]);
                const float4 hA = hr[0], hB = hr[1], hC = hr[2];
                const float h12 = hbuf[s][12];

                float a0 = fmaf(xA.x, wi[0], bias);
                float a1 = xA.y * wi[1];
                float a2 = xA.z * wi[2];
                float a3 = xA.w * wi[3];
                a0 = fmaf(xB.x, wi[4],  a0);
                a1 = fmaf(xB.y, wi[5],  a1);
                a2 = fmaf(xB.z, wi[6],  a2);
                a3 = fmaf(xB.w, wi[7],  a3);
                a0 = fmaf(xC.x, wi[8],  a0);
                a1 = fmaf(xC.y, wi[9],  a1);
                a2 = fmaf(xC.z, wi[10], a2);
                a3 = fmaf(xC.w, wi[11], a3);
                a0 = fmaf(x12,  wi[12], a0);

                a1 = fmaf(hA.x, wh[0],  a1);
                a2 = fmaf(hA.y, wh[1],  a2);
                a3 = fmaf(hA.z, wh[2],  a3);
                a0 = fmaf(hA.w, wh[3],  a0);
                a1 = fmaf(hB.x, wh[4],  a1);
                a2 = fmaf(hB.y, wh[5],  a2);
                a3 = fmaf(hB.z, wh[6],  a3);
                a0 = fmaf(hB.w, wh[7],  a0);
                a1 = fmaf(hC.x, wh[8],  a1);
                a2 = fmaf(hC.y, wh[9],  a2);
                a3 = fmaf(hC.z, wh[10], a3);
                a0 = fmaf(hC.w, wh[11], a0);
                a1 = fmaf(h12,  wh[12], a1);

                const float pre = (a0 + a1) + (a2 + a3);
                a = (g >= 26 && g < 39) ? tanh_fast(pre) : sigm(pre);
                act[s][g] = a;
            } else {
                // ---- x streaming lanes: publish x[tt+4], fetch x[tt+8] ----
                const int slot = (tt + 4) & 7;
                xrow[slot][s][k] = p[u];
                if (k == 0) xrow[slot][s][12] = q[u];
                if (tt + 8 < TT) {
                    p[u] = xb[(tt + 8) * 13 + k];
                    if (k == 0) q[u] = xb[(tt + 8) * 13 + 12];
                }
                // FC head for the PREVIOUS step's h (hbuf still holds h[tt-1]).
                if (g == 63 && tt > 0) {
                    out[(size_t)seq * TT + (tt - 1)] = fc_head(&hbuf[s][0], fcw, fcb);
                }
            }
            __syncthreads();   // gates visible

            // ---- phase 2: cell/hidden update by lanes 0..12 ----
            if (g < NH) {
                const float f_ = act[s][13 + g];
                const float gg = act[s][26 + g];
                const float o_ = act[s][39 + g];
                c = fmaf(f_, c, a * gg);          // a == sigmoid(i) for these lanes
                hbuf[s][g] = o_ * tanh_fast(c);
            }
            __syncthreads();   // h visible
        }
    }

    // Final step's FC output.
    if (g == 63) {
        out[(size_t)seq * TT + (TT - 1)] = fc_head(&hbuf[s][0], fcw, fcb);
    }
}

extern "C" void kernel_launch(void* const* d_in, const int* in_sizes, int n_in,
                              void* d_out, int out_size) {
    (void)in_sizes; (void)n_in; (void)out_size;
    const float* x    = (const float*)d_in[0];
    const float* W_ih = (const float*)d_in[1];
    const float* W_hh = (const float*)d_in[2];
    const float* b_ih = (const float*)d_in[3];
    const float* b_hh = (const float*)d_in[4];
    const float* fc_w = (const float*)d_in[5];
    const float* fc_b = (const float*)d_in[6];
    float* out = (float*)d_out;

    lstm_fused<<<NB / 2, 128>>>(x, W_ih, W_hh, b_ih, b_hh, fc_w, fc_b, out);
}

// round 3
// speedup vs baseline: 1.9872x; 1.9872x over previous
#include <cuda_runtime.h>

#define TT 2048
#define NB 512
#define NH 13
#define FULLM 0xFFFFFFFFu

__device__ __forceinline__ float sigm(float x) {
    return __fdividef(1.0f, 1.0f + __expf(-x));
}

// tanh(x) = 1 - 2/(1+e^{2x}); exact limits at +-inf, no NaN, ~1e-7 accuracy.
__device__ __forceinline__ float tanhe(float x) {
    return 1.0f - __fdividef(2.0f, 1.0f + __expf(2.0f * x));
}

__device__ __forceinline__ void cp_async4(void* smem_dst, const void* gmem_src) {
    unsigned saddr = (unsigned)__cvta_generic_to_shared(smem_dst);
    asm volatile("cp.async.ca.shared.global [%0], [%1], 4;\n"
                 :: "r"(saddr), "l"(gmem_src) : "memory");
}
__device__ __forceinline__ void cp_commit() {
    asm volatile("cp.async.commit_group;\n" ::: "memory");
}
__device__ __forceinline__ void cp_wait4() {
    asm volatile("cp.async.wait_group 4;\n" ::: "memory");
}

// FC head: strictly indices 0..12.
__device__ __forceinline__ float fc13(const float* hk, const float* fcw, float fcb) {
    float f0 = fmaf(hk[0], fcw[0], fcb);
    float f1 = hk[1] * fcw[1];
    float f2 = hk[2] * fcw[2];
    float f3 = hk[3] * fcw[3];
    f0 = fmaf(hk[4],  fcw[4],  f0);
    f1 = fmaf(hk[5],  fcw[5],  f1);
    f2 = fmaf(hk[6],  fcw[6],  f2);
    f3 = fmaf(hk[7],  fcw[7],  f3);
    f0 = fmaf(hk[8],  fcw[8],  f0);
    f1 = fmaf(hk[9],  fcw[9],  f1);
    f2 = fmaf(hk[10], fcw[10], f2);
    f3 = fmaf(hk[11], fcw[11], f3);
    f0 = fmaf(hk[12], fcw[12], f0);
    return sigm((f0 + f1) + (f2 + f3));
}

__global__ void __launch_bounds__(32)
lstm_warpseq(const float* __restrict__ x,
             const float* __restrict__ W_ih,
             const float* __restrict__ W_hh,
             const float* __restrict__ b_ih,
             const float* __restrict__ b_hh,
             const float* __restrict__ fc_w,
             const float* __restrict__ fc_b,
             float* __restrict__ out)
{
    // 8-deep ring of x rows, padded to 16 floats for LDS.128.
    __shared__ __align__(16) float xring[8][16];

    const int lane = threadIdx.x & 31;
    const int seq  = blockIdx.x;
    const float* xb = x + (size_t)seq * TT * NH;
    float* ob = out + (size_t)seq * TT;

    // Lane L < 26 owns gates L (A) and 26+L (B).
    // Lane j<13:  A = i_j, B = g_j.   Lane 13+j: A = f_j, B = o_j.
    float wiA[13], whA[13], wiB[13], whB[13];
    float biasA = 0.0f, biasB = 0.0f;
    if (lane < 26) {
        const int rA = lane, rB = lane + 26;
        #pragma unroll
        for (int k = 0; k < 13; k++) {
            wiA[k] = W_ih[rA * 13 + k];
            whA[k] = W_hh[rA * 13 + k];
            wiB[k] = W_ih[rB * 13 + k];
            whB[k] = W_hh[rB * 13 + k];
        }
        biasA = b_ih[rA] + b_hh[rA];
        biasB = b_ih[rB] + b_hh[rB];
    }
    float fcw[13];
    #pragma unroll
    for (int k = 0; k < 13; k++) fcw[k] = fc_w[k];
    const float fcb = fc_b[0];

    float h = 0.0f, c = 0.0f;

    // Prologue: stage x[0..3] (4 cp.async groups).
    #pragma unroll
    for (int t0 = 0; t0 < 4; t0++) {
        if (lane < 13) cp_async4(&xring[t0][lane], xb + t0 * 13 + lane);
        cp_commit();
    }

    for (int t = 0; t < TT; t++) {
        // Issue x[t+4] (group kept uniform even when empty past the end).
        if (lane < 13 && t + 4 < TT)
            cp_async4(&xring[(t + 4) & 7][lane], xb + (size_t)(t + 4) * 13 + lane);
        cp_commit();

        // Broadcast h_{t-1} (held on lanes 0..12) to everyone.
        float hk[13];
        #pragma unroll
        for (int k = 0; k < 13; k++) hk[k] = __shfl_sync(FULLM, h, k);

        // FC head for h_{t-1} on otherwise-idle lane 26 (hidden in shfl/MUFU gaps).
        if (lane == 26 && t > 0) {
            ob[t - 1] = fc13(hk, fcw, fcb);
        }

        // x[t] is 4 steps behind the freshest in-flight group.
        cp_wait4();
        __syncwarp();
        const float4* xr = reinterpret_cast<const float4*>(&xring[t & 7][0]);
        const float4 x0 = xr[0], x1 = xr[1], x2 = xr[2];
        float xv[13];
        xv[0] = x0.x; xv[1] = x0.y; xv[2]  = x0.z; xv[3]  = x0.w;
        xv[4] = x1.x; xv[5] = x1.y; xv[6]  = x1.z; xv[7]  = x1.w;
        xv[8] = x2.x; xv[9] = x2.y; xv[10] = x2.z; xv[11] = x2.w;
        xv[12] = xring[t & 7][12];

        // Gate pre-activations: 4-way accumulator split, x-part + h-part.
        float a0 = biasA, a1 = 0.0f, a2 = 0.0f, a3 = 0.0f;
        float e0 = biasB, e1 = 0.0f, e2 = 0.0f, e3 = 0.0f;
        #pragma unroll
        for (int k = 0; k < 13; k++) {
            switch (k & 3) {
                case 0: a0 = fmaf(xv[k], wiA[k], a0); e0 = fmaf(xv[k], wiB[k], e0); break;
                case 1: a1 = fmaf(xv[k], wiA[k], a1); e1 = fmaf(xv[k], wiB[k], e1); break;
                case 2: a2 = fmaf(xv[k], wiA[k], a2); e2 = fmaf(xv[k], wiB[k], e2); break;
                case 3: a3 = fmaf(xv[k], wiA[k], a3); e3 = fmaf(xv[k], wiB[k], e3); break;
            }
        }
        #pragma unroll
        for (int k = 0; k < 13; k++) {
            switch (k & 3) {
                case 0: a0 = fmaf(hk[k], whA[k], a0); e0 = fmaf(hk[k], whB[k], e0); break;
                case 1: a1 = fmaf(hk[k], whA[k], a1); e1 = fmaf(hk[k], whB[k], e1); break;
                case 2: a2 = fmaf(hk[k], whA[k], a2); e2 = fmaf(hk[k], whB[k], e2); break;
                case 3: a3 = fmaf(hk[k], whA[k], a3); e3 = fmaf(hk[k], whB[k], e3); break;
            }
        }
        const float preA = (a0 + a1) + (a2 + a3);   // lane j: pre_i ; lane 13+j: pre_f
        const float preB = (e0 + e1) + (e2 + e3);   // lane j: pre_g ; lane 13+j: pre_o

        // Ship pre_f / pre_o from lane 13+j to lane j.
        const float pf = __shfl_sync(FULLM, preA, (lane + 13) & 31);
        const float po = __shfl_sync(FULLM, preB, (lane + 13) & 31);

        if (lane < NH) {
            const float ig = sigm(preA);
            const float gg = tanhe(preB);
            const float fg = sigm(pf);
            const float og = sigm(po);
            c = fmaf(fg, c, ig * gg);
            h = og * tanhe(c);
        }
    }

    // Tail: emit FC(h_{TT-1}).
    float hk[13];
    #pragma unroll
    for (int k = 0; k < 13; k++) hk[k] = __shfl_sync(FULLM, h, k);
    if (lane == 26) {
        ob[TT - 1] = fc13(hk, fcw, fcb);
    }
}

extern "C" void kernel_launch(void* const* d_in, const int* in_sizes, int n_in,
                              void* d_out, int out_size) {
    (void)in_sizes; (void)n_in; (void)out_size;
    const float* x    = (const float*)d_in[0];
    const float* W_ih = (const float*)d_in[1];
    const float* W_hh = (const float*)d_in[2];
    const float* b_ih = (const float*)d_in[3];
    const float* b_hh = (const float*)d_in[4];
    const float* fc_w = (const float*)d_in[5];
    const float* fc_b = (const float*)d_in[6];
    float* out = (float*)d_out;

    lstm_warpseq<<<NB, 32>>>(x, W_ih, W_hh, b_ih, b_hh, fc_w, fc_b, out);
}

// round 4
// speedup vs baseline: 5.1650x; 2.5991x over previous
#include <cuda_runtime.h>

#define TT 2048
#define NB 512
#define FULLM 0xFFFFFFFFu
typedef unsigned long long ull;

__device__ __forceinline__ float tanhap(float x) {
    float r; asm("tanh.approx.f32 %0, %1;" : "=f"(r) : "f"(x)); return r;
}
__device__ __forceinline__ ull pk(float lo, float hi) {
    ull r; asm("mov.b64 %0, {%1, %2};" : "=l"(r) : "f"(lo), "f"(hi)); return r;
}
__device__ __forceinline__ void upk(ull v, float& lo, float& hi) {
    asm("mov.b64 {%0, %1}, %2;" : "=f"(lo), "=f"(hi) : "l"(v));
}
__device__ __forceinline__ ull fma2(ull a, ull b, ull c) {
    ull d; asm("fma.rn.f32x2 %0, %1, %2, %3;" : "=l"(d) : "l"(a), "l"(b), "l"(c)); return d;
}
__device__ __forceinline__ ull add2(ull a, ull b) {
    ull d; asm("add.rn.f32x2 %0, %1, %2;" : "=l"(d) : "l"(a), "l"(b)); return d;
}
__device__ __forceinline__ ull d2l(double d) { return (ull)__double_as_longlong(d); }

__device__ __forceinline__ void cp_async4(void* smem_dst, const void* gmem_src) {
    unsigned saddr = (unsigned)__cvta_generic_to_shared(smem_dst);
    asm volatile("cp.async.ca.shared.global [%0], [%1], 4;\n"
                 :: "r"(saddr), "l"(gmem_src) : "memory");
}
__device__ __forceinline__ void cp_commit() {
    asm volatile("cp.async.commit_group;\n" ::: "memory");
}
__device__ __forceinline__ void cp_wait4() {
    asm volatile("cp.async.wait_group 4;\n" ::: "memory");
}

// Dual-chain packed dot: 7 x-pairs + 7 h-pairs, bias folded into chain 0.
__device__ __forceinline__ float dot14(const ull* xp, const ull* hp,
                                       const ull* wx, const ull* wh,
                                       ull bias, ull zero) {
    ull a0 = fma2(xp[0], wx[0], bias);
    ull a1 = fma2(xp[1], wx[1], zero);
    a0 = fma2(xp[2], wx[2], a0);
    a1 = fma2(xp[3], wx[3], a1);
    a0 = fma2(xp[4], wx[4], a0);
    a1 = fma2(xp[5], wx[5], a1);
    a0 = fma2(xp[6], wx[6], a0);
    a1 = fma2(hp[0], wh[0], a1);
    a0 = fma2(hp[1], wh[1], a0);
    a1 = fma2(hp[2], wh[2], a1);
    a0 = fma2(hp[3], wh[3], a0);
    a1 = fma2(hp[4], wh[4], a1);
    a0 = fma2(hp[5], wh[5], a0);
    a1 = fma2(hp[6], wh[6], a1);
    ull s = add2(a0, a1);
    float lo, hi; upk(s, lo, hi);
    return lo + hi;
}

__device__ __forceinline__ float dot7(const ull* hp, const ull* w, ull bias, ull zero) {
    ull a0 = fma2(hp[0], w[0], bias);
    ull a1 = fma2(hp[1], w[1], zero);
    a0 = fma2(hp[2], w[2], a0);
    a1 = fma2(hp[3], w[3], a1);
    a0 = fma2(hp[4], w[4], a0);
    a1 = fma2(hp[5], w[5], a1);
    a0 = fma2(hp[6], w[6], a0);
    ull s = add2(a0, a1);
    float lo, hi; upk(s, lo, hi);
    return lo + hi;
}

__global__ void __launch_bounds__(32)
lstm_warpseq2(const float* __restrict__ x,
              const float* __restrict__ W_ih,
              const float* __restrict__ W_hh,
              const float* __restrict__ b_ih,
              const float* __restrict__ b_hh,
              const float* __restrict__ fc_w,
              const float* __restrict__ fc_b,
              float* __restrict__ out)
{
    // 8-deep x ring (rows padded to 16 floats; [13..15] stay zero) and
    // double-buffered h row ([13..15] stay zero).
    __shared__ __align__(16) float xring[8][16];
    __shared__ __align__(16) float hbuf[2][16];

    const int lane = threadIdx.x & 31;
    const int seq  = blockIdx.x;
    const float* xb = x + (size_t)seq * TT * 13;
    float* ob = out + (size_t)seq * TT;

    // Zero pad words once. cp.async only ever writes elements [0..12].
    if (lane < 24) xring[lane / 3][13 + lane % 3] = 0.0f;
    if (lane < 16) { hbuf[0][lane] = 0.0f; hbuf[1][lane] = 0.0f; }

    // Lane L<26 owns gates L (A) and 26+L (B).
    // Lane j<13:  A=i_j (sigm), B=g_j (tanh). Lane 13+j: A=f_j (sigm), B=o_j (sigm).
    float wiA[13], whA[13], wiB[13], whB[13];
    float biasA = 0.0f, biasB = 0.0f;
    {
        const bool act = (lane < 26);
        const int rA = act ? lane : 0, rB = act ? lane + 26 : 0;
        #pragma unroll
        for (int k = 0; k < 13; k++) {
            wiA[k] = act ? W_ih[rA * 13 + k] : 0.0f;
            whA[k] = act ? W_hh[rA * 13 + k] : 0.0f;
            wiB[k] = act ? W_ih[rB * 13 + k] : 0.0f;
            whB[k] = act ? W_hh[rB * 13 + k] : 0.0f;
        }
        if (act) { biasA = b_ih[rA] + b_hh[rA]; biasB = b_ih[rB] + b_hh[rB]; }
    }

    // Pack weights pairwise over k (7 pairs, last padded with 0).
    ull wxA[7], whAp[7], wxB[7], whBp[7], fcP[7];
    #pragma unroll
    for (int p = 0; p < 6; p++) {
        wxA[p]  = pk(wiA[2*p], wiA[2*p+1]);
        whAp[p] = pk(whA[2*p], whA[2*p+1]);
        wxB[p]  = pk(wiB[2*p], wiB[2*p+1]);
        whBp[p] = pk(whB[2*p], whB[2*p+1]);
        fcP[p]  = pk(fc_w[2*p], fc_w[2*p+1]);
    }
    wxA[6]  = pk(wiA[12], 0.0f);
    whAp[6] = pk(whA[12], 0.0f);
    wxB[6]  = pk(wiB[12], 0.0f);
    whBp[6] = pk(whB[12], 0.0f);
    fcP[6]  = pk(fc_w[12], 0.0f);

    const ull biasPA = pk(biasA, 0.0f);
    const ull biasPB = pk(biasB, 0.0f);
    const ull fcbP   = pk(fc_b[0], 0.0f);
    const ull zero64 = pk(0.0f, 0.0f);

    // Per-lane activation constants for the B gate (tanh vs sigmoid), branch-free.
    const float sB = (lane < 13) ? 1.0f : 0.5f;   // pre-scale
    const float mB = sB;                          // post-scale
    const float aB = (lane < 13) ? 0.0f : 0.5f;   // post-offset

    float h = 0.0f, c = 0.0f;

    // Prologue: stage x[0..3] as 4 cp.async groups.
    #pragma unroll
    for (int t0 = 0; t0 < 4; t0++) {
        if (lane < 13) cp_async4(&xring[t0][lane], xb + t0 * 13 + lane);
        cp_commit();
    }

    for (int t = 0; t < TT; t += 8) {
        #pragma unroll
        for (int u = 0; u < 8; u++) {
            const int tt    = t + u;
            const int slot  = u;              // tt & 7
            const int wslot = (u + 4) & 7;    // (tt+4) & 7
            const int hbr   = (u + 1) & 1;    // holds h_{tt-1}
            const int hbw   = u & 1;

            if (lane < 13 && tt + 4 < TT)
                cp_async4(&xring[wslot][lane], xb + (size_t)(tt + 4) * 13 + lane);
            cp_commit();
            cp_wait4();
            __syncwarp();

            // x[tt] pairs (broadcast LDS, pre-packed in register pairs).
            const double2* xr = reinterpret_cast<const double2*>(&xring[slot][0]);
            const double2 q0 = xr[0], q1 = xr[1], q2 = xr[2];
            const double  q3 = *reinterpret_cast<const double*>(&xring[slot][12]);
            ull xp[7] = { d2l(q0.x), d2l(q0.y), d2l(q1.x), d2l(q1.y),
                          d2l(q2.x), d2l(q2.y), d2l(q3) };

            // h_{tt-1} pairs.
            const double2* hr = reinterpret_cast<const double2*>(&hbuf[hbr][0]);
            const double2 r0 = hr[0], r1 = hr[1], r2 = hr[2];
            const double  r3 = *reinterpret_cast<const double*>(&hbuf[hbr][12]);
            ull hp[7] = { d2l(r0.x), d2l(r0.y), d2l(r1.x), d2l(r1.y),
                          d2l(r2.x), d2l(r2.y), d2l(r3) };

            const float preA = dot14(xp, hp, wxA, whAp, biasPA, zero64);
            const float preB = dot14(xp, hp, wxB, whBp, biasPB, zero64);

            // FC head on h_{tt-1} (off the recurrence chain).
            const float fcpre = dot7(hp, fcP, fcbP, zero64);
            const float outv  = fmaf(0.5f, tanhap(0.5f * fcpre), 0.5f);
            if (lane == 26 && tt > 0) ob[tt - 1] = outv;

            // Activations (MUFU.TANH); B-gate kind selected by per-lane constants.
            const float actA = fmaf(0.5f, tanhap(0.5f * preA), 0.5f);
            const float actB = fmaf(mB, tanhap(sB * preB), aB);

            // Ship activated f/o from lane 13+j to lane j.
            const float fg = __shfl_sync(FULLM, actA, (lane + 13) & 31);
            const float og = __shfl_sync(FULLM, actB, (lane + 13) & 31);

            // Update (meaningful on lanes 0..12; harmless elsewhere).
            c = fmaf(fg, c, actA * actB);
            h = og * tanhap(c);
            if (lane < 13) hbuf[hbw][lane] = h;
        }
    }

    // Tail: FC on h_{TT-1} (stored in hbuf[(TT-1)&1] = hbuf[1]).
    __syncwarp();
    {
        const double2* hr = reinterpret_cast<const double2*>(&hbuf[1][0]);
        const double2 r0 = hr[0], r1 = hr[1], r2 = hr[2];
        const double  r3 = *reinterpret_cast<const double*>(&hbuf[1][12]);
        ull hp[7] = { d2l(r0.x), d2l(r0.y), d2l(r1.x), d2l(r1.y),
                      d2l(r2.x), d2l(r2.y), d2l(r3) };
        const float fcpre = dot7(hp, fcP, fcbP, zero64);
        const float outv  = fmaf(0.5f, tanhap(0.5f * fcpre), 0.5f);
        if (lane == 26) ob[TT - 1] = outv;
    }
}

extern "C" void kernel_launch(void* const* d_in, const int* in_sizes, int n_in,
                              void* d_out, int out_size) {
    (void)in_sizes; (void)n_in; (void)out_size;
    const float* x    = (const float*)d_in[0];
    const float* W_ih = (const float*)d_in[1];
    const float* W_hh = (const float*)d_in[2];
    const float* b_ih = (const float*)d_in[3];
    const float* b_hh = (const float*)d_in[4];
    const float* fc_w = (const float*)d_in[5];
    const float* fc_b = (const float*)d_in[6];
    float* out = (float*)d_out;

    lstm_warpseq2<<<NB, 32>>>(x, W_ih, W_hh, b_ih, b_hh, fc_w, fc_b, out);
}

// round 5
// speedup vs baseline: 5.8105x; 1.1250x over previous
#include <cuda_runtime.h>

#define TT 2048
#define NB 512
#define FULLM 0xFFFFFFFFu
typedef unsigned long long ull;

__device__ __forceinline__ float tanhap(float x) {
    float r; asm("tanh.approx.f32 %0, %1;" : "=f"(r) : "f"(x)); return r;
}
__device__ __forceinline__ ull pk(float lo, float hi) {
    ull r; asm("mov.b64 %0, {%1, %2};" : "=l"(r) : "f"(lo), "f"(hi)); return r;
}
__device__ __forceinline__ void upk(ull v, float& lo, float& hi) {
    asm("mov.b64 {%0, %1}, %2;" : "=f"(lo), "=f"(hi) : "l"(v));
}
__device__ __forceinline__ ull fma2(ull a, ull b, ull c) {
    ull d; asm("fma.rn.f32x2 %0, %1, %2, %3;" : "=l"(d) : "l"(a), "l"(b), "l"(c)); return d;
}
__device__ __forceinline__ ull add2(ull a, ull b) {
    ull d; asm("add.rn.f32x2 %0, %1, %2;" : "=l"(d) : "l"(a), "l"(b)); return d;
}
__device__ __forceinline__ ull d2l(double d) { return (ull)__double_as_longlong(d); }

__device__ __forceinline__ void cp_async4(void* smem_dst, const void* gmem_src) {
    unsigned saddr = (unsigned)__cvta_generic_to_shared(smem_dst);
    asm volatile("cp.async.ca.shared.global [%0], [%1], 4;\n"
                 :: "r"(saddr), "l"(gmem_src) : "memory");
}
__device__ __forceinline__ void cp_commit() {
    asm volatile("cp.async.commit_group;\n" ::: "memory");
}
__device__ __forceinline__ void cp_wait4() {
    asm volatile("cp.async.wait_group 4;\n" ::: "memory");
}

// 4-chain packed dot; x terms first (available early), h terms last (depth <=2
// from h-arrival), then 2-level add tree.
__device__ __forceinline__ float dotg(const ull* xp, const ull* hp,
                                      const ull* wx, const ull* wh,
                                      ull bias, ull z) {
    ull c0 = fma2(xp[0], wx[0], bias);
    ull c1 = fma2(xp[1], wx[1], z);
    ull c2 = fma2(xp[2], wx[2], z);
    ull c3 = fma2(xp[3], wx[3], z);
    c0 = fma2(xp[4], wx[4], c0);
    c1 = fma2(xp[5], wx[5], c1);
    c2 = fma2(xp[6], wx[6], c2);
    c3 = fma2(hp[0], wh[0], c3);
    c0 = fma2(hp[1], wh[1], c0);
    c1 = fma2(hp[2], wh[2], c1);
    c2 = fma2(hp[3], wh[3], c2);
    c3 = fma2(hp[4], wh[4], c3);
    c0 = fma2(hp[5], wh[5], c0);
    c1 = fma2(hp[6], wh[6], c1);
    ull s = add2(add2(c0, c1), add2(c2, c3));
    float lo, hi; upk(s, lo, hi);
    return lo + hi;
}

// h-only dot (tail FC).
__device__ __forceinline__ float dot7(const ull* hp, const ull* w, ull bias, ull z) {
    ull a0 = fma2(hp[0], w[0], bias);
    ull a1 = fma2(hp[1], w[1], z);
    a0 = fma2(hp[2], w[2], a0);
    a1 = fma2(hp[3], w[3], a1);
    a0 = fma2(hp[4], w[4], a0);
    a1 = fma2(hp[5], w[5], a1);
    a0 = fma2(hp[6], w[6], a0);
    ull s = add2(a0, a1);
    float lo, hi; upk(s, lo, hi);
    return lo + hi;
}

__device__ __forceinline__ void ldpairs(const float* row, ull* p) {
    const double2* r = reinterpret_cast<const double2*>(row);
    const double2 q0 = r[0], q1 = r[1], q2 = r[2];
    const double  q3 = *reinterpret_cast<const double*>(row + 12);
    p[0] = d2l(q0.x); p[1] = d2l(q0.y); p[2] = d2l(q1.x); p[3] = d2l(q1.y);
    p[4] = d2l(q2.x); p[5] = d2l(q2.y); p[6] = d2l(q3);
}

__global__ void __launch_bounds__(32)
lstm_warpseq3(const float* __restrict__ x,
              const float* __restrict__ W_ih,
              const float* __restrict__ W_hh,
              const float* __restrict__ b_ih,
              const float* __restrict__ b_hh,
              const float* __restrict__ fc_w,
              const float* __restrict__ fc_b,
              float* __restrict__ out)
{
    __shared__ __align__(16) float xring[8][16];   // pads [13..15] = 0
    __shared__ __align__(16) float hbuf[2][16];    // pads [13..15] = 0

    const int lane = threadIdx.x & 31;
    const int seq  = blockIdx.x;
    const float* xb = x + (size_t)seq * TT * 13;
    float* ob = out + (size_t)seq * TT;

    if (lane < 24) xring[lane / 3][13 + lane % 3] = 0.0f;
    if (lane < 16) { hbuf[0][lane] = 0.0f; hbuf[1][lane] = 0.0f; }

    // Gate assignment: lane L<26: A = gate L (sigmoid; i for L<13, f for L>=13),
    // B = gate 26+L (g=tanh for L<13, o=sigmoid for L>=13).
    // Lane 26: B-dot doubles as the FC head (x-weights 0, h-weights 0.5*fc_w).
    // Sigmoid pre-scale 0.5 folded into weights; act = m*tanh(pre) + a.
    float wiA[13], whA[13], wiB[13], whB[13];
    float biasA = 0.0f, biasB = 0.0f;
    {
        const bool g26 = (lane < 26);
        const float sA = 0.5f;                          // A gates all sigmoid
        const float sB = (lane < 13) ? 1.0f : 0.5f;     // g: tanh, o/fc: sigmoid
        const int rA = g26 ? lane : 0;
        const int rB = g26 ? lane + 26 : 0;
        #pragma unroll
        for (int k = 0; k < 13; k++) {
            wiA[k] = g26 ? sA * W_ih[rA * 13 + k] : 0.0f;
            whA[k] = g26 ? sA * W_hh[rA * 13 + k] : 0.0f;
            wiB[k] = g26 ? sB * W_ih[rB * 13 + k] : 0.0f;
            whB[k] = g26 ? sB * W_hh[rB * 13 + k] : 0.0f;
        }
        if (g26) {
            biasA = sA * (b_ih[rA] + b_hh[rA]);
            biasB = sB * (b_ih[rB] + b_hh[rB]);
        }
        if (lane == 26) {
            #pragma unroll
            for (int k = 0; k < 13; k++) { wiB[k] = 0.0f; whB[k] = 0.5f * fc_w[k]; }
            biasB = 0.5f * fc_b[0];
        }
    }

    ull wxA[7], whAp[7], wxB[7], whBp[7];
    #pragma unroll
    for (int p = 0; p < 6; p++) {
        wxA[p]  = pk(wiA[2*p], wiA[2*p+1]);
        whAp[p] = pk(whA[2*p], whA[2*p+1]);
        wxB[p]  = pk(wiB[2*p], wiB[2*p+1]);
        whBp[p] = pk(whB[2*p], whB[2*p+1]);
    }
    wxA[6]  = pk(wiA[12], 0.0f);
    whAp[6] = pk(whA[12], 0.0f);
    wxB[6]  = pk(wiB[12], 0.0f);
    whBp[6] = pk(whB[12], 0.0f);

    const ull biasPA = pk(biasA, 0.0f);
    const ull biasPB = pk(biasB, 0.0f);
    const ull zero64 = pk(0.0f, 0.0f);

    const float mB = (lane < 13) ? 1.0f : 0.5f;
    const float aB = (lane < 13) ? 0.0f : 0.5f;

    float h = 0.0f, c = 0.0f;

    // Prologue: stage x rows 0..4 (5 commit groups), then pull row 0 to regs.
    #pragma unroll
    for (int t0 = 0; t0 < 5; t0++) {
        if (lane < 13) cp_async4(&xring[t0][lane], xb + t0 * 13 + lane);
        cp_commit();
    }
    cp_wait4();
    __syncwarp();
    ull xcur[7];
    ldpairs(&xring[0][0], xcur);

    for (int t = 0; t < TT; t += 8) {
        #pragma unroll
        for (int u = 0; u < 8; u++) {
            const int tt    = t + u;
            const int wslot = (u + 5) & 7;    // (tt+5) & 7
            const int nslot = (u + 1) & 7;    // (tt+1) & 7
            const int hbr   = (u + 1) & 1;    // holds h_{tt-1}
            const int hbw   = u & 1;

            if (lane < 13 && tt + 5 < TT)
                cp_async4(&xring[wslot][lane], xb + (size_t)(tt + 5) * 13 + lane);
            cp_commit();
            cp_wait4();          // guarantees row tt+1 resident
            __syncwarp();        // x visibility + h_{tt-1} STS visibility

            // h_{tt-1} pairs (critical), then next x row to registers.
            ull hp[7];
            ldpairs(&hbuf[hbr][0], hp);
            ull xnxt[7];
            ldpairs(&xring[nslot][0], xnxt);

            const float preA = dotg(xcur, hp, wxA, whAp, biasPA, zero64);
            const float preB = dotg(xcur, hp, wxB, whBp, biasPB, zero64);

            const float actA = fmaf(0.5f, tanhap(preA), 0.5f);   // sigm (i / f)
            const float actB = fmaf(mB,   tanhap(preB), aB);     // g / o / FC

            // Lane 26's actB == sigm(fc(h_{tt-1})): emit output tt-1.
            if (lane == 26 && tt > 0) ob[tt - 1] = actB;

            // Ship activated f / o from lane 13+j to lane j.
            const float fg = __shfl_sync(FULLM, actA, (lane + 13) & 31);
            const float og = __shfl_sync(FULLM, actB, (lane + 13) & 31);

            c = fmaf(fg, c, actA * actB);
            h = og * tanhap(c);
            if (lane < 13) hbuf[hbw][lane] = h;

            #pragma unroll
            for (int p = 0; p < 7; p++) xcur[p] = xnxt[p];
        }
    }

    // Tail: ob[TT-1] = sigm(fc(h_{TT-1})); h_{TT-1} lives in hbuf[(TT-1)&1]=hbuf[1].
    __syncwarp();
    {
        ull hp[7];
        ldpairs(&hbuf[1][0], hp);
        const float pre  = dot7(hp, whBp, biasPB, zero64);   // lane 26: 0.5*fc
        const float outv = fmaf(0.5f, tanhap(pre), 0.5f);
        if (lane == 26) ob[TT - 1] = outv;
    }
}

extern "C" void kernel_launch(void* const* d_in, const int* in_sizes, int n_in,
                              void* d_out, int out_size) {
    (void)in_sizes; (void)n_in; (void)out_size;
    const float* x    = (const float*)d_in[0];
    const float* W_ih = (const float*)d_in[1];
    const float* W_hh = (const float*)d_in[2];
    const float* b_ih = (const float*)d_in[3];
    const float* b_hh = (const float*)d_in[4];
    const float* fc_w = (const float*)d_in[5];
    const float* fc_b = (const float*)d_in[6];
    float* out = (float*)d_out;

    lstm_warpseq3<<<NB, 32>>>(x, W_ih, W_hh, b_ih, b_hh, fc_w, fc_b, out);
}